// round 4
// baseline (speedup 1.0000x reference)
#include <cuda_runtime.h>
#include <cstdint>

#define HSZ   512
#define ISZ   256
#define BSZ   64
#define NBLK  128
#define NTHR  256
#define WHD_STR 1028   // 1024 dup floats + 4 pad  (stride ≡ 4 mod 32 → conflict-free row broadcasts)
#define WID_STR 516    // 512 dup floats + 4 pad
#define RSTR    68     // reduction row stride (floats)
#define RWSTR   1088   // 16*RSTR : per-ksplit stride
#define EPSBN 1e-5f

// smem layout (floats)
#define OFF_WHD  0
#define OFF_WID  (OFF_WHD + 16*WHD_STR)        // 16448
#define OFF_ST   (OFF_WID + 16*WID_STR)        // +8256 -> 24704
#define OFF_SG   (OFF_ST + 3*4096)             // +12288 -> 36992   (stage triple buffer; reused for reduction: needs 8*1088=8704 <= 12288)
#define OFF_CST  (OFF_SG + 16*64)              // +1024 -> 38016
#define SMEM_FLOATS (OFF_CST + 96)
#define SMEM_BYTES  (SMEM_FLOATS*4)            // ~149 KB

__device__ float g_h[2][HSZ*BSZ];              // double-buffered hidden state
__device__ unsigned g_arrive;
__device__ unsigned g_release;

typedef unsigned long long ull;

__device__ __forceinline__ void unpack2(ull v, float &lo, float &hi){
    asm("mov.b64 {%0, %1}, %2;" : "=f"(lo), "=f"(hi) : "l"(v));
}
__device__ __forceinline__ void ffma2(ull &acc, ull a, ull b){
    asm("fma.rn.f32x2 %0, %1, %2, %0;" : "+l"(acc) : "l"(a), "l"(b));
}
__device__ __forceinline__ void addf2(ull &acc, ull a){
    asm("add.rn.f32x2 %0, %0, %1;" : "+l"(acc) : "l"(a));
}
__device__ __forceinline__ void cp16(uint32_t dst, const void* src){
    asm volatile("cp.async.cg.shared.global [%0], [%1], 16;" :: "r"(dst), "l"(src));
}
__device__ __forceinline__ float sigm(float x){
    return 1.0f / (1.0f + __expf(-x));
}

// 8 consecutive k for 2 rows x 16 cols (8 f32x2 per row per gemm).
// wr0/wr1: duplicated-weight pointers (k-dup pairs), st: staged state [k][64] (pre-offset to this warp's k-slice)
__device__ __forceinline__ void gemm8(const float* __restrict__ st,
                                      const float* __restrict__ wr0,
                                      const float* __restrict__ wr1,
                                      int c0, ull* __restrict__ a0, ull* __restrict__ a1)
{
    #pragma unroll
    for (int g = 0; g < 2; g++){
        const int k0 = g*4;
        ulonglong2 wa = *(const ulonglong2*)(wr0 + k0*2);       // row0: w[k0],w[k0+1] (dup pairs)
        ulonglong2 wb = *(const ulonglong2*)(wr0 + k0*2 + 4);   // row0: w[k0+2],w[k0+3]
        ulonglong2 ua = *(const ulonglong2*)(wr1 + k0*2);       // row1
        ulonglong2 ub = *(const ulonglong2*)(wr1 + k0*2 + 4);
        #pragma unroll
        for (int kk = 0; kk < 4; kk++){
            const float* sp = st + (k0+kk)*64 + c0;
            ulonglong2 s0 = *(const ulonglong2*)(sp);
            ulonglong2 s1 = *(const ulonglong2*)(sp + 4);
            ulonglong2 s2 = *(const ulonglong2*)(sp + 8);
            ulonglong2 s3 = *(const ulonglong2*)(sp + 12);
            ull w0v = (kk==0)?wa.x:(kk==1)?wa.y:(kk==2)?wb.x:wb.y;
            ull w1v = (kk==0)?ua.x:(kk==1)?ua.y:(kk==2)?ub.x:ub.y;
            ffma2(a0[0], w0v, s0.x); ffma2(a0[1], w0v, s0.y);
            ffma2(a0[2], w0v, s1.x); ffma2(a0[3], w0v, s1.y);
            ffma2(a0[4], w0v, s2.x); ffma2(a0[5], w0v, s2.y);
            ffma2(a0[6], w0v, s3.x); ffma2(a0[7], w0v, s3.y);
            ffma2(a1[0], w1v, s0.x); ffma2(a1[1], w1v, s0.y);
            ffma2(a1[2], w1v, s1.x); ffma2(a1[3], w1v, s1.y);
            ffma2(a1[4], w1v, s2.x); ffma2(a1[5], w1v, s2.y);
            ffma2(a1[6], w1v, s3.x); ffma2(a1[7], w1v, s3.y);
        }
    }
}

extern "C" __global__ void __launch_bounds__(NTHR, 1)
lstm_bn_kernel(const float* __restrict__ x,
               const float* __restrict__ Wih,
               const float* __restrict__ Whh,
               const float* __restrict__ bias,
               const float* __restrict__ gIH, const float* __restrict__ bIH,
               const float* __restrict__ gHH, const float* __restrict__ bHH,
               const float* __restrict__ gC,  const float* __restrict__ bC,
               float* __restrict__ out, int T)
{
    extern __shared__ float sm[];
    float* whd    = sm + OFF_WHD;
    float* wid    = sm + OFF_WID;
    float* stage  = sm + OFF_ST;
    float* sg     = sm + OFF_SG;
    float* ghh_s  = sm + OFF_CST;       // 16
    float* bhh_s  = ghh_s + 16;
    float* gih_s  = bhh_s + 16;
    float* bih_s  = gih_s + 16;
    float* bias_s = bih_s + 16;
    float* gc_s   = bias_s + 16;        // 4
    float* bc_s   = gc_s + 4;           // 4

    const int tid  = threadIdx.x;
    const int blk  = blockIdx.x;
    const int w    = tid >> 5;          // warp id = k-split slice 0..7
    const int lane = tid & 31;
    const int rg   = lane >> 2;         // row group 0..7 -> rows {rg, rg+8}
    const int cg   = lane & 3;          // col group 0..3 -> cols cg*16..+15
    const int c0   = cg * 16;

    // ---- preload weights, DUPLICATED (each value twice, adjacent)
    // block owns gate rows l=0..15 -> global row (l>>2)*512 + blk*4 + (l&3)
    for (int idx = tid; idx < 16*HSZ; idx += NTHR){
        int l = idx >> 9, k = idx & 511;
        int grow = (l >> 2) * HSZ + blk*4 + (l & 3);
        float v = Whh[(size_t)grow * HSZ + k];
        whd[l*WHD_STR + 2*k]     = v;
        whd[l*WHD_STR + 2*k + 1] = v;
    }
    for (int idx = tid; idx < 16*ISZ; idx += NTHR){
        int l = idx >> 8, k = idx & 255;
        int grow = (l >> 2) * HSZ + blk*4 + (l & 3);
        float v = Wih[(size_t)grow * ISZ + k];
        wid[l*WID_STR + 2*k]     = v;
        wid[l*WID_STR + 2*k + 1] = v;
    }
    if (tid < 16){
        int grow = (tid >> 2) * HSZ + blk*4 + (tid & 3);
        ghh_s[tid] = gHH[grow]; bhh_s[tid] = bHH[grow];
        gih_s[tid] = gIH[grow]; bih_s[tid] = bIH[grow];
        bias_s[tid] = bias[grow];
    }
    if (tid < 4){ gc_s[tid] = gC[blk*4 + tid]; bc_s[tid] = bC[blk*4 + tid]; }

    // ---- zero h buffer 0 (this block's slice: 256 floats)
    g_h[0][blk * NTHR + tid] = 0.f;
    __syncthreads();

    unsigned gen0 = 0, my_gen = 0;
    if (tid == 0) gen0 = *((volatile unsigned*)&g_release);

    auto gridsync = [&](){
        __syncthreads();
        if (tid == 0){
            my_gen++;
            __threadfence();
            unsigned a = atomicAdd(&g_arrive, 1u);
            if (a == (unsigned)(NBLK - 1)){
                atomicExch(&g_arrive, 0u);
                __threadfence();
                atomicAdd(&g_release, 1u);
            } else {
                while ( (*((volatile unsigned*)&g_release)) - gen0 < my_gen ) { }
            }
        }
        __syncthreads();
    };

    gridsync();   // h buffer zeroed everywhere before step 0

    const uint32_t stBase = (uint32_t)__cvta_generic_to_shared(stage);
    const float inv64 = 1.0f / 64.0f;
    float creg0 = 0.f, creg1 = 0.f;     // cell state rows (warps 0-3 only)

    // weight base pointers for this thread's two rows (k-offset added per chunk)
    const float* whd0 = whd + rg*WHD_STR + w*16;
    const float* whd1 = whd + (rg+8)*WHD_STR + w*16;
    const float* wid0 = wid + rg*WID_STR + w*16;
    const float* wid1 = wid + (rg+8)*WID_STR + w*16;
    const int stOff = w * 8 * 64;       // this warp's k-slice within a staged chunk

    for (int t = 0; t < T; t++){
        const float* hrd = g_h[t & 1];
        float*       hwr = g_h[(t + 1) & 1];
        const float* xt  = x + (size_t)t * (ISZ*BSZ);

        ull accA0[8], accA1[8], accB0[8], accB1[8];
        #pragma unroll
        for (int i = 0; i < 8; i++){ accA0[i]=0; accA1[i]=0; accB0[i]=0; accB1[i]=0; }

        // prefetch chunk 0 (h, k=0..63) into buf 0
        {
            uint32_t d = stBase;
            #pragma unroll
            for (int i = 0; i < 4; i++)
                cp16(d + (tid + i*256)*16, hrd + (tid + i*256)*4);
            asm volatile("cp.async.commit_group;");
        }

        for (int ci = 0; ci < 12; ci++){
            if (ci < 11){
                int cn = ci + 1;
                const float* src = (cn < 8) ? (hrd + cn*4096) : (xt + (cn - 8)*4096);
                uint32_t d = stBase + (uint32_t)((cn % 3) * 4096) * 4u;
                #pragma unroll
                for (int i = 0; i < 4; i++)
                    cp16(d + (tid + i*256)*16, src + (tid + i*256)*4);
                asm volatile("cp.async.commit_group;");
                asm volatile("cp.async.wait_group 1;");
            } else {
                asm volatile("cp.async.wait_group 0;");
            }
            __syncthreads();   // triple buffer: single barrier per chunk

            const float* st = stage + (ci % 3) * 4096 + stOff;
            if (ci < 8)
                gemm8(st, whd0 + ci*128,     whd1 + ci*128,     c0, accA0, accA1);
            else
                gemm8(st, wid0 + (ci-8)*128, wid1 + (ci-8)*128, c0, accB0, accB1);
        }

        __syncthreads();   // all stage reads done; reuse stage for reduction

        float* red = stage;
        float vA[4], vB[4];

        // ---- reduction pass A (W_hh @ h partials over 8 k-splits)
        #pragma unroll
        for (int ri = 0; ri < 2; ri++){
            const ull* srcp = ri ? accA1 : accA0;
            int l = rg + ri*8;
            #pragma unroll
            for (int j = 0; j < 4; j++)
                *(ulonglong2*)(red + w*RWSTR + l*RSTR + c0 + j*4) =
                    make_ulonglong2(srcp[2*j], srcp[2*j+1]);
        }
        __syncthreads();
        {
            const int lr = tid >> 4, c4 = (tid & 15) * 4;
            const float* rp = red + lr*RSTR + c4;
            ulonglong2 s = *(const ulonglong2*)rp;
            ull sx = s.x, sy = s.y;
            #pragma unroll
            for (int ww = 1; ww < 8; ww++){
                ulonglong2 p = *(const ulonglong2*)(rp + ww*RWSTR);
                addf2(sx, p.x); addf2(sy, p.y);
            }
            unpack2(sx, vA[0], vA[1]); unpack2(sy, vA[2], vA[3]);
        }
        __syncthreads();

        // ---- reduction pass B (W_ih @ x partials)
        #pragma unroll
        for (int ri = 0; ri < 2; ri++){
            const ull* srcp = ri ? accB1 : accB0;
            int l = rg + ri*8;
            #pragma unroll
            for (int j = 0; j < 4; j++)
                *(ulonglong2*)(red + w*RWSTR + l*RSTR + c0 + j*4) =
                    make_ulonglong2(srcp[2*j], srcp[2*j+1]);
        }
        __syncthreads();
        {
            const int lr = tid >> 4, c4 = (tid & 15) * 4;
            const float* rp = red + lr*RSTR + c4;
            ulonglong2 s = *(const ulonglong2*)rp;
            ull sx = s.x, sy = s.y;
            #pragma unroll
            for (int ww = 1; ww < 8; ww++){
                ulonglong2 p = *(const ulonglong2*)(rp + ww*RWSTR);
                addf2(sx, p.x); addf2(sy, p.y);
            }
            unpack2(sx, vB[0], vB[1]); unpack2(sy, vB[2], vB[3]);
        }

        // ---- phase A: per-gate-row batchnorm; thread owns row rt=tid>>4, cols (tid&15)*4..+3
        {
            const int rt = tid >> 4, c4 = (tid & 15) * 4;
            float sA = vA[0]+vA[1]+vA[2]+vA[3];
            float qA = vA[0]*vA[0]+vA[1]*vA[1]+vA[2]*vA[2]+vA[3]*vA[3];
            float sB = vB[0]+vB[1]+vB[2]+vB[3];
            float qB = vB[0]*vB[0]+vB[1]*vB[1]+vB[2]*vB[2]+vB[3]*vB[3];
            #pragma unroll
            for (int off = 1; off < 16; off <<= 1){
                sA += __shfl_xor_sync(0xffffffffu, sA, off);
                qA += __shfl_xor_sync(0xffffffffu, qA, off);
                sB += __shfl_xor_sync(0xffffffffu, sB, off);
                qB += __shfl_xor_sync(0xffffffffu, qB, off);
            }
            float muA = sA*inv64, muB = sB*inv64;
            float rsA = rsqrtf(qA*inv64 - muA*muA + EPSBN);
            float rsB = rsqrtf(qB*inv64 - muB*muB + EPSBN);
            float ga = ghh_s[rt]*rsA, gb = gih_s[rt]*rsB;
            float cadd = bhh_s[rt] + bih_s[rt] + bias_s[rt] - muA*ga - muB*gb;
            #pragma unroll
            for (int j = 0; j < 4; j++)
                sg[rt*64 + c4 + j] = fmaf(vA[j], ga, fmaf(vB[j], gb, cadd));
        }
        __syncthreads();

        // ---- phase B: gates + cell + c-BN + h  (warps 0-3; warp w owns h-row blk*4+w)
        if (w < 4){
            float iv0 = sg[( 0 + w)*64 + lane], iv1 = sg[( 0 + w)*64 + lane + 32];
            float fv0 = sg[( 4 + w)*64 + lane], fv1 = sg[( 4 + w)*64 + lane + 32];
            float gv0 = sg[( 8 + w)*64 + lane], gv1 = sg[( 8 + w)*64 + lane + 32];
            float ov0 = sg[(12 + w)*64 + lane], ov1 = sg[(12 + w)*64 + lane + 32];

            creg0 = sigm(fv0)*creg0 + sigm(iv0)*tanhf(gv0);
            creg1 = sigm(fv1)*creg1 + sigm(iv1)*tanhf(gv1);

            float sc = creg0 + creg1;
            float qc = creg0*creg0 + creg1*creg1;
            #pragma unroll
            for (int off = 16; off >= 1; off >>= 1){
                sc += __shfl_xor_sync(0xffffffffu, sc, off);
                qc += __shfl_xor_sync(0xffffffffu, qc, off);
            }
            float mu = sc*inv64;
            float rs = rsqrtf(qc*inv64 - mu*mu + EPSBN);
            float gcv = gc_s[w]*rs;
            float bcv = bc_s[w] - mu*gcv;
            float h0v = sigm(ov0) * tanhf(fmaf(creg0, gcv, bcv));
            float h1v = sigm(ov1) * tanhf(fmaf(creg1, gcv, bcv));

            int rowg = blk*4 + w;
            hwr[rowg*64 + lane]      = h0v;
            hwr[rowg*64 + lane + 32] = h1v;
            float* op = out + (size_t)t * (HSZ*BSZ) + rowg*64;
            op[lane]      = h0v;
            op[lane + 32] = h1v;
        }

        gridsync();   // h visible chip-wide before next step's loads
    }
}

extern "C" void kernel_launch(void* const* d_in, const int* in_sizes, int n_in,
                              void* d_out, int out_size)
{
    const float* x    = (const float*)d_in[0];
    const float* Wih  = (const float*)d_in[1];
    const float* Whh  = (const float*)d_in[2];
    const float* bias = (const float*)d_in[3];
    const float* gIH  = (const float*)d_in[4];
    const float* bIH  = (const float*)d_in[5];
    const float* gHH  = (const float*)d_in[6];
    const float* bHH  = (const float*)d_in[7];
    const float* gC   = (const float*)d_in[8];
    const float* bC   = (const float*)d_in[9];
    float* out = (float*)d_out;

    int T = in_sizes[0] / (ISZ * BSZ);   // 2048

    cudaFuncSetAttribute(lstm_bn_kernel,
                         cudaFuncAttributeMaxDynamicSharedMemorySize, SMEM_BYTES);
    lstm_bn_kernel<<<NBLK, NTHR, SMEM_BYTES>>>(x, Wih, Whh, bias,
                                               gIH, bIH, gHH, bHH, gC, bC,
                                               out, T);
}

// round 5
// speedup vs baseline: 2.1553x; 2.1553x over previous
#include <cuda_runtime.h>
#include <cstdint>

#define HSZ   512
#define ISZ   256
#define BSZ   64
#define NBLK  128
#define NTHR  128
#define WHD_STR 1028   // 1024 dup floats + 4 pad (≡4 mod 32 → conflict-free row loads)
#define WID_STR 516    // 512 dup floats + 4 pad
#define EPSBN 1e-5f

// smem layout (floats)
#define OFF_WHD  0
#define OFF_WID  (OFF_WHD + 16*WHD_STR)        // 16448
#define OFF_ST   (OFF_WID + 16*WID_STR)        // +8256 -> 24704
#define OFF_SG   (OFF_ST + 3*4096)             // +12288 -> 36992 (triple buffer)
#define OFF_CST  (OFF_SG + 16*64)              // +1024 -> 38016
#define SMEM_FLOATS (OFF_CST + 96)
#define SMEM_BYTES  (SMEM_FLOATS*4)            // ~149 KB

__device__ float g_h[2][HSZ*BSZ];              // double-buffered hidden state
__device__ unsigned g_arrive;
__device__ unsigned g_release;

typedef unsigned long long ull;

__device__ __forceinline__ void unpack2(ull v, float &lo, float &hi){
    asm("mov.b64 {%0, %1}, %2;" : "=f"(lo), "=f"(hi) : "l"(v));
}
__device__ __forceinline__ void ffma2(ull &acc, ull a, ull b){
    asm("fma.rn.f32x2 %0, %1, %2, %0;" : "+l"(acc) : "l"(a), "l"(b));
}
__device__ __forceinline__ void cp16(uint32_t dst, const void* src){
    asm volatile("cp.async.cg.shared.global [%0], [%1], 16;" :: "r"(dst), "l"(src));
}
__device__ __forceinline__ float sigm(float x){
    return 1.0f / (1.0f + __expf(-x));
}

// one 64-k slice: thread does 2 rows x 4 cols. Weights duplicated in smem
// (LDS.128 -> two ready f32x2 broadcast pairs; NO pack MOVs).
__device__ __forceinline__ void gemm_dup(const float* __restrict__ st,
                                         const float* __restrict__ w0,
                                         const float* __restrict__ w1,
                                         int c0,
                                         ull &a00, ull &a01, ull &a10, ull &a11)
{
    #pragma unroll
    for (int kk = 0; kk < 64; kk += 4){
        ulonglong2 p0 = *(const ulonglong2*)(w0 + kk*2);       // row0: (w[k],w[k]),(w[k+1],w[k+1])
        ulonglong2 p1 = *(const ulonglong2*)(w0 + kk*2 + 4);   // row0: k+2,k+3
        ulonglong2 q0 = *(const ulonglong2*)(w1 + kk*2);       // row1
        ulonglong2 q1 = *(const ulonglong2*)(w1 + kk*2 + 4);
        ulonglong2 h0 = *(const ulonglong2*)(st + (kk+0)*64 + c0);
        ulonglong2 h1 = *(const ulonglong2*)(st + (kk+1)*64 + c0);
        ulonglong2 h2 = *(const ulonglong2*)(st + (kk+2)*64 + c0);
        ulonglong2 h3 = *(const ulonglong2*)(st + (kk+3)*64 + c0);
        ffma2(a00, p0.x, h0.x); ffma2(a01, p0.x, h0.y);
        ffma2(a10, q0.x, h0.x); ffma2(a11, q0.x, h0.y);
        ffma2(a00, p0.y, h1.x); ffma2(a01, p0.y, h1.y);
        ffma2(a10, q0.y, h1.x); ffma2(a11, q0.y, h1.y);
        ffma2(a00, p1.x, h2.x); ffma2(a01, p1.x, h2.y);
        ffma2(a10, q1.x, h2.x); ffma2(a11, q1.x, h2.y);
        ffma2(a00, p1.y, h3.x); ffma2(a01, p1.y, h3.y);
        ffma2(a10, q1.y, h3.x); ffma2(a11, q1.y, h3.y);
    }
}

extern "C" __global__ void __launch_bounds__(NTHR, 1)
lstm_bn_kernel(const float* __restrict__ x,
               const float* __restrict__ Wih,
               const float* __restrict__ Whh,
               const float* __restrict__ bias,
               const float* __restrict__ gIH, const float* __restrict__ bIH,
               const float* __restrict__ gHH, const float* __restrict__ bHH,
               const float* __restrict__ gC,  const float* __restrict__ bC,
               float* __restrict__ out, int T)
{
    extern __shared__ float sm[];
    float* whd    = sm + OFF_WHD;
    float* wid    = sm + OFF_WID;
    float* stage  = sm + OFF_ST;
    float* sg     = sm + OFF_SG;
    float* ghh_s  = sm + OFF_CST;       // 16
    float* bhh_s  = ghh_s + 16;
    float* gih_s  = bhh_s + 16;
    float* bih_s  = gih_s + 16;
    float* bias_s = bih_s + 16;
    float* gc_s   = bias_s + 16;        // 4
    float* bc_s   = gc_s + 4;           // 4

    const int tid = threadIdx.x;
    const int blk = blockIdx.x;
    const int ct  = tid & 15;           // col group 0..15 -> cols ct*4..+3
    const int rt  = tid >> 4;           // 0..7 -> rows {2rt, 2rt+1}
    const int c0  = ct * 4;
    const int l0  = rt * 2;

    // ---- preload weights, DUPLICATED (each value twice, adjacent)
    // block owns gate rows l=0..15 -> global row (l>>2)*512 + blk*4 + (l&3)
    for (int idx = tid; idx < 16*HSZ; idx += NTHR){
        int l = idx >> 9, k = idx & 511;
        int grow = (l >> 2) * HSZ + blk*4 + (l & 3);
        float v = Whh[(size_t)grow * HSZ + k];
        whd[l*WHD_STR + 2*k]     = v;
        whd[l*WHD_STR + 2*k + 1] = v;
    }
    for (int idx = tid; idx < 16*ISZ; idx += NTHR){
        int l = idx >> 8, k = idx & 255;
        int grow = (l >> 2) * HSZ + blk*4 + (l & 3);
        float v = Wih[(size_t)grow * ISZ + k];
        wid[l*WID_STR + 2*k]     = v;
        wid[l*WID_STR + 2*k + 1] = v;
    }
    if (tid < 16){
        int grow = (tid >> 2) * HSZ + blk*4 + (tid & 3);
        ghh_s[tid] = gHH[grow]; bhh_s[tid] = bHH[grow];
        gih_s[tid] = gIH[grow]; bih_s[tid] = bIH[grow];
        bias_s[tid] = bias[grow];
    }
    if (tid < 4){ gc_s[tid] = gC[blk*4 + tid]; bc_s[tid] = bC[blk*4 + tid]; }

    // ---- zero h buffer 0 (this block's slice: 256 floats)
    {
        int base = blk * ((HSZ*BSZ) / NBLK);
        g_h[0][base + tid]       = 0.f;
        g_h[0][base + tid + 128] = 0.f;
    }
    __syncthreads();

    unsigned gen0 = 0, my_gen = 0;
    if (tid == 0) gen0 = *((volatile unsigned*)&g_release);

    auto gridsync = [&](){
        __syncthreads();
        if (tid == 0){
            my_gen++;
            __threadfence();
            unsigned a = atomicAdd(&g_arrive, 1u);
            if (a == (unsigned)(NBLK - 1)){
                atomicExch(&g_arrive, 0u);
                __threadfence();
                atomicAdd(&g_release, 1u);
            } else {
                while ( (*((volatile unsigned*)&g_release)) - gen0 < my_gen ) { }
            }
        }
        __syncthreads();
    };

    gridsync();   // h buffer zeroed everywhere before step 0

    const uint32_t stBase = (uint32_t)__cvta_generic_to_shared(stage);
    const float inv64 = 1.0f / 64.0f;
    float creg0 = 0.f, creg1 = 0.f;     // cell state, block-local rows forever
    const int wwarp = tid >> 5;         // 0..3 -> local h-row
    const int lane  = tid & 31;

    const float* wh0 = whd + l0*WHD_STR;
    const float* wh1 = wh0 + WHD_STR;
    const float* wi0 = wid + l0*WID_STR;
    const float* wi1 = wi0 + WID_STR;

    for (int t = 0; t < T; t++){
        const float* hrd = g_h[t & 1];
        float*       hwr = g_h[(t + 1) & 1];
        const float* xt  = x + (size_t)t * (ISZ*BSZ);

        ull aA00=0, aA01=0, aA10=0, aA11=0;  // W_hh @ h
        ull aB00=0, aB01=0, aB10=0, aB11=0;  // W_ih @ x_t

        // prefetch chunk 0 (h, k=0..63) into buf 0
        {
            uint32_t d = stBase;
            #pragma unroll
            for (int i = 0; i < 8; i++)
                cp16(d + (tid + i*128)*16, hrd + (tid + i*128)*4);
            asm volatile("cp.async.commit_group;");
        }

        for (int ci = 0; ci < 12; ci++){
            if (ci < 11){
                int cn = ci + 1;
                const float* src = (cn < 8) ? (hrd + cn*4096) : (xt + (cn - 8)*4096);
                uint32_t d = stBase + (uint32_t)((cn % 3) * 4096) * 4u;
                #pragma unroll
                for (int i = 0; i < 8; i++)
                    cp16(d + (tid + i*128)*16, src + (tid + i*128)*4);
                asm volatile("cp.async.commit_group;");
                asm volatile("cp.async.wait_group 1;");
            } else {
                asm volatile("cp.async.wait_group 0;");
            }
            __syncthreads();   // triple buffer: single barrier per chunk

            const float* st = stage + (ci % 3) * 4096;
            if (ci < 8)
                gemm_dup(st, wh0 + ci*128,     wh1 + ci*128,     c0, aA00, aA01, aA10, aA11);
            else
                gemm_dup(st, wi0 + (ci-8)*128, wi1 + (ci-8)*128, c0, aB00, aB01, aB10, aB11);
        }

        // ---- phase A: per-gate-row batchnorm (rows {l0,l0+1}, cols c0..c0+3)
        float vA0[4], vA1[4], vB0[4], vB1[4];
        unpack2(aA00, vA0[0], vA0[1]); unpack2(aA01, vA0[2], vA0[3]);
        unpack2(aA10, vA1[0], vA1[1]); unpack2(aA11, vA1[2], vA1[3]);
        unpack2(aB00, vB0[0], vB0[1]); unpack2(aB01, vB0[2], vB0[3]);
        unpack2(aB10, vB1[0], vB1[1]); unpack2(aB11, vB1[2], vB1[3]);

        #pragma unroll
        for (int r = 0; r < 2; r++){
            float* vA = r ? vA1 : vA0;
            float* vB = r ? vB1 : vB0;
            const int l = l0 + r;
            float sA = vA[0]+vA[1]+vA[2]+vA[3];
            float qA = vA[0]*vA[0]+vA[1]*vA[1]+vA[2]*vA[2]+vA[3]*vA[3];
            float sB = vB[0]+vB[1]+vB[2]+vB[3];
            float qB = vB[0]*vB[0]+vB[1]*vB[1]+vB[2]*vB[2]+vB[3]*vB[3];
            #pragma unroll
            for (int off = 1; off < 16; off <<= 1){
                sA += __shfl_xor_sync(0xffffffffu, sA, off);
                qA += __shfl_xor_sync(0xffffffffu, qA, off);
                sB += __shfl_xor_sync(0xffffffffu, sB, off);
                qB += __shfl_xor_sync(0xffffffffu, qB, off);
            }
            float muA = sA*inv64, muB = sB*inv64;
            float rsA = rsqrtf(qA*inv64 - muA*muA + EPSBN);
            float rsB = rsqrtf(qB*inv64 - muB*muB + EPSBN);
            float ga = ghh_s[l]*rsA, gb = gih_s[l]*rsB;
            float cadd = bhh_s[l] + bih_s[l] + bias_s[l] - muA*ga - muB*gb;
            #pragma unroll
            for (int j = 0; j < 4; j++)
                sg[l*64 + c0 + j] = fmaf(vA[j], ga, fmaf(vB[j], gb, cadd));
        }
        __syncthreads();

        // ---- phase B: gates + cell + c-BN + h (warp w owns h-row blk*4+w)
        {
            float iv0 = sg[( 0 + wwarp)*64 + lane], iv1 = sg[( 0 + wwarp)*64 + lane + 32];
            float fv0 = sg[( 4 + wwarp)*64 + lane], fv1 = sg[( 4 + wwarp)*64 + lane + 32];
            float gv0 = sg[( 8 + wwarp)*64 + lane], gv1 = sg[( 8 + wwarp)*64 + lane + 32];
            float ov0 = sg[(12 + wwarp)*64 + lane], ov1 = sg[(12 + wwarp)*64 + lane + 32];

            creg0 = sigm(fv0)*creg0 + sigm(iv0)*tanhf(gv0);
            creg1 = sigm(fv1)*creg1 + sigm(iv1)*tanhf(gv1);

            float sc = creg0 + creg1;
            float qc = creg0*creg0 + creg1*creg1;
            #pragma unroll
            for (int off = 16; off >= 1; off >>= 1){
                sc += __shfl_xor_sync(0xffffffffu, sc, off);
                qc += __shfl_xor_sync(0xffffffffu, qc, off);
            }
            float mu = sc*inv64;
            float rs = rsqrtf(qc*inv64 - mu*mu + EPSBN);
            float gcv = gc_s[wwarp]*rs;
            float bcv = bc_s[wwarp] - mu*gcv;
            float h0v = sigm(ov0) * tanhf(fmaf(creg0, gcv, bcv));
            float h1v = sigm(ov1) * tanhf(fmaf(creg1, gcv, bcv));

            int rowg = blk*4 + wwarp;
            hwr[rowg*64 + lane]      = h0v;
            hwr[rowg*64 + lane + 32] = h1v;
            float* op = out + (size_t)t * (HSZ*BSZ) + rowg*64;
            op[lane]      = h0v;
            op[lane + 32] = h1v;
        }

        gridsync();   // h visible chip-wide before next step's loads
    }
}

extern "C" void kernel_launch(void* const* d_in, const int* in_sizes, int n_in,
                              void* d_out, int out_size)
{
    const float* x    = (const float*)d_in[0];
    const float* Wih  = (const float*)d_in[1];
    const float* Whh  = (const float*)d_in[2];
    const float* bias = (const float*)d_in[3];
    const float* gIH  = (const float*)d_in[4];
    const float* bIH  = (const float*)d_in[5];
    const float* gHH  = (const float*)d_in[6];
    const float* bHH  = (const float*)d_in[7];
    const float* gC   = (const float*)d_in[8];
    const float* bC   = (const float*)d_in[9];
    float* out = (float*)d_out;

    int T = in_sizes[0] / (ISZ * BSZ);   // 2048

    cudaFuncSetAttribute(lstm_bn_kernel,
                         cudaFuncAttributeMaxDynamicSharedMemorySize, SMEM_BYTES);
    lstm_bn_kernel<<<NBLK, NTHR, SMEM_BYTES>>>(x, Wih, Whh, bias,
                                               gIH, bIH, gHH, bHH, gC, bC,
                                               out, T);
}

// round 9
// speedup vs baseline: 2.2469x; 1.0425x over previous
#include <cuda_runtime.h>
#include <cstdint>

#define HSZ   512
#define ISZ   256
#define BSZ   64
#define NBLK  128
#define NTHR  256
#define WHD_STR 1028   // 1024 dup floats + 4 pad
#define WID_STR 516    // 512 dup floats + 4 pad
#define PSTR    68     // partial row stride
#define EPSBN 1e-5f

// smem layout (floats)
#define OFF_WHD  0
#define OFF_WID  (OFF_WHD + 16*WHD_STR)        // 16448
#define OFF_ST   (OFF_WID + 16*WID_STR)        // 24704  (6 slots x 4096 floats = 96KB)
#define OFF_PA   (OFF_ST + 6*4096)             // 49280  (2 wg x 16 x 68)
#define OFF_PB   (OFF_PA + 2*16*PSTR)          // 51456
#define OFF_SG   (OFF_PB + 2*16*PSTR)          // 53632
#define OFF_CST  (OFF_SG + 16*64)              // 54656
#define SMEM_FLOATS (OFF_CST + 96)
#define SMEM_BYTES  (SMEM_FLOATS*4)            // 219008 B ≈ 214 KB (< 227KB cap)

#define SLOT_BYTES 16384u                      // 4096 floats per chunk slot

__device__ float g_h[2][HSZ*BSZ];              // double-buffered hidden state
__device__ unsigned g_arrive;
__device__ unsigned g_release;

typedef unsigned long long ull;

__device__ __forceinline__ void unpack2(ull v, float &lo, float &hi){
    asm("mov.b64 {%0, %1}, %2;" : "=f"(lo), "=f"(hi) : "l"(v));
}
__device__ __forceinline__ void ffma2(ull &acc, ull a, ull b){
    asm("fma.rn.f32x2 %0, %1, %2, %0;" : "+l"(acc) : "l"(a), "l"(b));
}
__device__ __forceinline__ void addf2(ull &acc, ull a){
    asm("add.rn.f32x2 %0, %0, %1;" : "+l"(acc) : "l"(a));
}
__device__ __forceinline__ void cp16(uint32_t dst, const void* src){
    asm volatile("cp.async.cg.shared.global [%0], [%1], 16;" :: "r"(dst), "l"(src));
}
__device__ __forceinline__ float sigm(float x){
    return 1.0f / (1.0f + __expf(-x));
}

// one 64-k slice: 2 rows x 4 cols, duplicated weights (no pack MOVs)
__device__ __forceinline__ void gemm_dup(const float* __restrict__ st,
                                         const float* __restrict__ w0,
                                         const float* __restrict__ w1,
                                         int c0,
                                         ull &a00, ull &a01, ull &a10, ull &a11)
{
    #pragma unroll
    for (int kk = 0; kk < 64; kk += 4){
        ulonglong2 p0 = *(const ulonglong2*)(w0 + kk*2);
        ulonglong2 p1 = *(const ulonglong2*)(w0 + kk*2 + 4);
        ulonglong2 q0 = *(const ulonglong2*)(w1 + kk*2);
        ulonglong2 q1 = *(const ulonglong2*)(w1 + kk*2 + 4);
        ulonglong2 h0 = *(const ulonglong2*)(st + (kk+0)*64 + c0);
        ulonglong2 h1 = *(const ulonglong2*)(st + (kk+1)*64 + c0);
        ulonglong2 h2 = *(const ulonglong2*)(st + (kk+2)*64 + c0);
        ulonglong2 h3 = *(const ulonglong2*)(st + (kk+3)*64 + c0);
        ffma2(a00, p0.x, h0.x); ffma2(a01, p0.x, h0.y);
        ffma2(a10, q0.x, h0.x); ffma2(a11, q0.x, h0.y);
        ffma2(a00, p0.y, h1.x); ffma2(a01, p0.y, h1.y);
        ffma2(a10, q0.y, h1.x); ffma2(a11, q0.y, h1.y);
        ffma2(a00, p1.x, h2.x); ffma2(a01, p1.x, h2.y);
        ffma2(a10, q1.x, h2.x); ffma2(a11, q1.x, h2.y);
        ffma2(a00, p1.y, h3.x); ffma2(a01, p1.y, h3.y);
        ffma2(a10, q1.y, h3.x); ffma2(a11, q1.y, h3.y);
    }
}

extern "C" __global__ void __launch_bounds__(NTHR, 1)
lstm_bn_kernel(const float* __restrict__ x,
               const float* __restrict__ Wih,
               const float* __restrict__ Whh,
               const float* __restrict__ bias,
               const float* __restrict__ gIH, const float* __restrict__ bIH,
               const float* __restrict__ gHH, const float* __restrict__ bHH,
               const float* __restrict__ gC,  const float* __restrict__ bC,
               float* __restrict__ out, int T)
{
    extern __shared__ float sm[];
    float* whd    = sm + OFF_WHD;
    float* wid    = sm + OFF_WID;
    float* stage  = sm + OFF_ST;
    float* pA     = sm + OFF_PA;        // [2][16][PSTR]
    float* pB     = sm + OFF_PB;
    float* sg     = sm + OFF_SG;
    float* ghh_s  = sm + OFF_CST;       // 16
    float* bhh_s  = ghh_s + 16;
    float* gih_s  = bhh_s + 16;
    float* bih_s  = gih_s + 16;
    float* bias_s = bih_s + 16;
    float* gc_s   = bias_s + 16;        // 4
    float* bc_s   = gc_s + 4;           // 4

    const int tid  = threadIdx.x;
    const int blk  = blockIdx.x;
    const int wg   = tid >> 7;          // warp-group 0/1 (k-split half)
    const int wtid = tid & 127;
    const int ct   = wtid & 15;         // col group -> cols ct*4..+3
    const int rt   = wtid >> 4;         // 0..7 -> rows {2rt, 2rt+1}
    const int c0   = ct * 4;
    const int l0   = rt * 2;

    // ---- preload weights, DUPLICATED (each value twice, adjacent)
    for (int idx = tid; idx < 16*HSZ; idx += NTHR){
        int l = idx >> 9, k = idx & 511;
        int grow = (l >> 2) * HSZ + blk*4 + (l & 3);
        float v = Whh[(size_t)grow * HSZ + k];
        whd[l*WHD_STR + 2*k]     = v;
        whd[l*WHD_STR + 2*k + 1] = v;
    }
    for (int idx = tid; idx < 16*ISZ; idx += NTHR){
        int l = idx >> 8, k = idx & 255;
        int grow = (l >> 2) * HSZ + blk*4 + (l & 3);
        float v = Wih[(size_t)grow * ISZ + k];
        wid[l*WID_STR + 2*k]     = v;
        wid[l*WID_STR + 2*k + 1] = v;
    }
    if (tid < 16){
        int grow = (tid >> 2) * HSZ + blk*4 + (tid & 3);
        ghh_s[tid] = gHH[grow]; bhh_s[tid] = bHH[grow];
        gih_s[tid] = gIH[grow]; bih_s[tid] = bIH[grow];
        bias_s[tid] = bias[grow];
    }
    if (tid < 4){ gc_s[tid] = gC[blk*4 + tid]; bc_s[tid] = bC[blk*4 + tid]; }

    // ---- zero h buffer 0 (this block's slice: 256 floats)
    g_h[0][blk * NTHR + tid] = 0.f;
    __syncthreads();

    unsigned gen0 = 0, my_gen = 0;
    if (tid == 0) gen0 = *((volatile unsigned*)&g_release);

    auto gridsync = [&](){
        __syncthreads();
        if (tid == 0){
            my_gen++;
            __threadfence();
            unsigned a = atomicAdd(&g_arrive, 1u);
            if (a == (unsigned)(NBLK - 1)){
                atomicExch(&g_arrive, 0u);
                __threadfence();
                atomicAdd(&g_release, 1u);
            } else {
                while ( (*((volatile unsigned*)&g_release)) - gen0 < my_gen ) { }
            }
        }
        __syncthreads();
    };

    gridsync();   // h buffer zeroed everywhere before step 0

    const uint32_t stBase = (uint32_t)__cvta_generic_to_shared(stage);
    const float inv64 = 1.0f / 64.0f;
    float creg0 = 0.f, creg1 = 0.f;     // cell state (threads tid<128 only)
    const int wwarp = tid >> 5;
    const int lane  = tid & 31;

    const float* wh0 = whd + l0*WHD_STR;
    const float* wh1 = wh0 + WHD_STR;
    const float* wi0 = wid + l0*WID_STR;
    const float* wi1 = wi0 + WID_STR;

    for (int t = 0; t < T; t++){
        const float* hrd = g_h[t & 1];
        float*       hwr = g_h[(t + 1) & 1];
        const float* xt  = x + (size_t)t * (ISZ*BSZ);

        ull aA00=0, aA01=0, aA10=0, aA11=0;  // W_hh @ h partial (this wg's chunks)
        ull aB00=0, aB01=0, aB10=0, aB11=0;  // W_ih @ x partial

        // prefetch chunks 0,1 (h k=0..127) into slots 0,1 — 32KB, 8 cp16/thread
        {
            #pragma unroll
            for (int j = 0; j < 4; j++){
                cp16(stBase +              (uint32_t)(tid + j*256)*16u, hrd +        (tid + j*256)*4);
                cp16(stBase + SLOT_BYTES + (uint32_t)(tid + j*256)*16u, hrd + 4096 + (tid + j*256)*4);
            }
            asm volatile("cp.async.commit_group;");
        }

        // 6 rounds; round r: wg g computes chunk 2r+g; prefetch chunks 2r+2,2r+3
        for (int r = 0; r < 6; r++){
            if (r < 5){
                int cA = 2*r + 2, cB = 2*r + 3;
                const float* srcA = (cA < 8) ? (hrd + cA*4096) : (xt + (cA-8)*4096);
                const float* srcB = (cB < 8) ? (hrd + cB*4096) : (xt + (cB-8)*4096);
                uint32_t dA = stBase + (uint32_t)(cA % 6) * SLOT_BYTES;
                uint32_t dB = stBase + (uint32_t)(cB % 6) * SLOT_BYTES;
                #pragma unroll
                for (int j = 0; j < 4; j++){
                    cp16(dA + (uint32_t)(tid + j*256)*16u, srcA + (tid + j*256)*4);
                    cp16(dB + (uint32_t)(tid + j*256)*16u, srcB + (tid + j*256)*4);
                }
                asm volatile("cp.async.commit_group;");
                asm volatile("cp.async.wait_group 1;");
            } else {
                asm volatile("cp.async.wait_group 0;");
            }
            __syncthreads();   // one barrier per round (6-slot ring: round-r prefetch
                               // targets slots last read in round r-2, fenced by r-1's barrier)

            int c = 2*r + wg;
            const float* st = stage + (c % 6) * 4096;
            if (c < 8)
                gemm_dup(st, wh0 + c*128,     wh1 + c*128,     c0, aA00, aA01, aA10, aA11);
            else
                gemm_dup(st, wi0 + (c-8)*128, wi1 + (c-8)*128, c0, aB00, aB01, aB10, aB11);
        }

        // ---- write per-wg partials to smem (4 STS.128 each)
        {
            float* ap = pA + wg*(16*PSTR);
            float* bp = pB + wg*(16*PSTR);
            *(ulonglong2*)(ap + (l0  )*PSTR + c0) = make_ulonglong2(aA00, aA01);
            *(ulonglong2*)(ap + (l0+1)*PSTR + c0) = make_ulonglong2(aA10, aA11);
            *(ulonglong2*)(bp + (l0  )*PSTR + c0) = make_ulonglong2(aB00, aB01);
            *(ulonglong2*)(bp + (l0+1)*PSTR + c0) = make_ulonglong2(aB10, aB11);
        }
        __syncthreads();

        // ---- phase A: reduce 2-way + per-gate-row batchnorm
        // thread owns row rr = tid>>4 (0..15), cols c4 = (tid&15)*4
        {
            const int rr = tid >> 4, c4 = (tid & 15) * 4;
            ulonglong2 xa0 = *(const ulonglong2*)(pA + rr*PSTR + c4);
            ulonglong2 xa1 = *(const ulonglong2*)(pA + 16*PSTR + rr*PSTR + c4);
            ulonglong2 xb0 = *(const ulonglong2*)(pB + rr*PSTR + c4);
            ulonglong2 xb1 = *(const ulonglong2*)(pB + 16*PSTR + rr*PSTR + c4);
            addf2(xa0.x, xa1.x); addf2(xa0.y, xa1.y);
            addf2(xb0.x, xb1.x); addf2(xb0.y, xb1.y);

            float vA[4], vB[4];
            unpack2(xa0.x, vA[0], vA[1]); unpack2(xa0.y, vA[2], vA[3]);
            unpack2(xb0.x, vB[0], vB[1]); unpack2(xb0.y, vB[2], vB[3]);

            float sA = vA[0]+vA[1]+vA[2]+vA[3];
            float qA = vA[0]*vA[0]+vA[1]*vA[1]+vA[2]*vA[2]+vA[3]*vA[3];
            float sB = vB[0]+vB[1]+vB[2]+vB[3];
            float qB = vB[0]*vB[0]+vB[1]*vB[1]+vB[2]*vB[2]+vB[3]*vB[3];
            #pragma unroll
            for (int off = 1; off < 16; off <<= 1){
                sA += __shfl_xor_sync(0xffffffffu, sA, off);
                qA += __shfl_xor_sync(0xffffffffu, qA, off);
                sB += __shfl_xor_sync(0xffffffffu, sB, off);
                qB += __shfl_xor_sync(0xffffffffu, qB, off);
            }
            float muA = sA*inv64, muB = sB*inv64;
            float rsA = rsqrtf(qA*inv64 - muA*muA + EPSBN);
            float rsB = rsqrtf(qB*inv64 - muB*muB + EPSBN);
            float ga = ghh_s[rr]*rsA, gb = gih_s[rr]*rsB;
            float cadd = bhh_s[rr] + bih_s[rr] + bias_s[rr] - muA*ga - muB*gb;
            #pragma unroll
            for (int j = 0; j < 4; j++)
                sg[rr*64 + c4 + j] = fmaf(vA[j], ga, fmaf(vB[j], gb, cadd));
        }
        __syncthreads();

        // ---- phase B: gates + cell + c-BN + h (warps 0-3; warp w owns h-row blk*4+w)
        if (wwarp < 4){
            float iv0 = sg[( 0 + wwarp)*64 + lane], iv1 = sg[( 0 + wwarp)*64 + lane + 32];
            float fv0 = sg[( 4 + wwarp)*64 + lane], fv1 = sg[( 4 + wwarp)*64 + lane + 32];
            float gv0 = sg[( 8 + wwarp)*64 + lane], gv1 = sg[( 8 + wwarp)*64 + lane + 32];
            float ov0 = sg[(12 + wwarp)*64 + lane], ov1 = sg[(12 + wwarp)*64 + lane + 32];

            creg0 = sigm(fv0)*creg0 + sigm(iv0)*tanhf(gv0);
            creg1 = sigm(fv1)*creg1 + sigm(iv1)*tanhf(gv1);

            float sc = creg0 + creg1;
            float qc = creg0*creg0 + creg1*creg1;
            #pragma unroll
            for (int off = 16; off >= 1; off >>= 1){
                sc += __shfl_xor_sync(0xffffffffu, sc, off);
                qc += __shfl_xor_sync(0xffffffffu, qc, off);
            }
            float mu = sc*inv64;
            float rs = rsqrtf(qc*inv64 - mu*mu + EPSBN);
            float gcv = gc_s[wwarp]*rs;
            float bcv = bc_s[wwarp] - mu*gcv;
            float h0v = sigm(ov0) * tanhf(fmaf(creg0, gcv, bcv));
            float h1v = sigm(ov1) * tanhf(fmaf(creg1, gcv, bcv));

            int rowg = blk*4 + wwarp;
            hwr[rowg*64 + lane]      = h0v;
            hwr[rowg*64 + lane + 32] = h1v;
            float* op = out + (size_t)t * (HSZ*BSZ) + rowg*64;
            op[lane]      = h0v;
            op[lane + 32] = h1v;
        }

        gridsync();   // h visible chip-wide before next step's loads
    }
}

extern "C" void kernel_launch(void* const* d_in, const int* in_sizes, int n_in,
                              void* d_out, int out_size)
{
    const float* x    = (const float*)d_in[0];
    const float* Wih  = (const float*)d_in[1];
    const float* Whh  = (const float*)d_in[2];
    const float* bias = (const float*)d_in[3];
    const float* gIH  = (const float*)d_in[4];
    const float* bIH  = (const float*)d_in[5];
    const float* gHH  = (const float*)d_in[6];
    const float* bHH  = (const float*)d_in[7];
    const float* gC   = (const float*)d_in[8];
    const float* bC   = (const float*)d_in[9];
    float* out = (float*)d_out;

    int T = in_sizes[0] / (ISZ * BSZ);   // 2048

    cudaFuncSetAttribute(lstm_bn_kernel,
                         cudaFuncAttributeMaxDynamicSharedMemorySize, SMEM_BYTES);
    lstm_bn_kernel<<<NBLK, NTHR, SMEM_BYTES>>>(x, Wih, Whh, bias,
                                               gIH, bIH, gHH, bHH, gC, bC,
                                               out, T);
}

// round 11
// speedup vs baseline: 3.1252x; 1.3909x over previous
#include <cuda_runtime.h>
#include <cstdint>

#define HSZ   512
#define ISZ   256
#define BSZ   64
#define NBLK  128
#define NTHR  256
#define WHD_STR 1028   // 1024 dup floats + 4 pad (rowg*WHD_STR ≡ rowg*4 mod 32 → conflict-free)
#define WID_STR 516
#define PSTR    68     // partial row stride
#define EPSBN 1e-5f

// smem layout (floats)
#define OFF_WHD  0
#define OFF_WID  (OFF_WHD + 16*WHD_STR)        // 16448
#define OFF_ST   (OFF_WID + 16*WID_STR)        // 24704 (6 slots x 4096 floats = 96KB; reused for partials)
#define OFF_SG   (OFF_ST + 6*4096)             // 49280
#define OFF_CST  (OFF_SG + 16*64)              // 50304
#define SMEM_FLOATS (OFF_CST + 96)
#define SMEM_BYTES  (SMEM_FLOATS*4)            // ~197 KB (< 227KB cap)

#define SLOT_BYTES 16384u

__device__ float g_h[2][HSZ*BSZ];
__device__ unsigned g_arrive;
__device__ unsigned g_release;

typedef unsigned long long ull;

__device__ __forceinline__ void unpack2(ull v, float &lo, float &hi){
    asm("mov.b64 {%0, %1}, %2;" : "=f"(lo), "=f"(hi) : "l"(v));
}
__device__ __forceinline__ void ffma2(ull &acc, ull a, ull b){
    asm("fma.rn.f32x2 %0, %1, %2, %0;" : "+l"(acc) : "l"(a), "l"(b));
}
__device__ __forceinline__ void addf2(ull &acc, ull a){
    asm("add.rn.f32x2 %0, %0, %1;" : "+l"(acc) : "l"(a));
}
__device__ __forceinline__ void cp16(uint32_t dst, const void* src){
    asm volatile("cp.async.cg.shared.global [%0], [%1], 16;" :: "r"(dst), "l"(src));
}
__device__ __forceinline__ float sigm(float x){
    return 1.0f / (1.0f + __expf(-x));
}

// 8-k slice of one chunk: thread does 4 rows x 8 cols (16 acc f32x2).
// st: slot base + this warp's k-slice offset; wb: weight base for row rowg at this slice's k (dup floats).
// wstr: weight row stride. acc[j*4+p]: row j, col-pair p (p0,p1 -> cols c0..c0+3; p2,p3 -> c0+32..+35)
__device__ __forceinline__ void gemm_slice(const float* __restrict__ st,
                                           const float* __restrict__ wb, int wstr,
                                           int c0, ull* __restrict__ acc)
{
    #pragma unroll
    for (int g = 0; g < 2; g++){
        ulonglong2 w0l = *(const ulonglong2*)(wb + 0*4*wstr + g*8);
        ulonglong2 w0h = *(const ulonglong2*)(wb + 0*4*wstr + g*8 + 4);
        ulonglong2 w1l = *(const ulonglong2*)(wb + 1*4*wstr + g*8);
        ulonglong2 w1h = *(const ulonglong2*)(wb + 1*4*wstr + g*8 + 4);
        ulonglong2 w2l = *(const ulonglong2*)(wb + 2*4*wstr + g*8);
        ulonglong2 w2h = *(const ulonglong2*)(wb + 2*4*wstr + g*8 + 4);
        ulonglong2 w3l = *(const ulonglong2*)(wb + 3*4*wstr + g*8);
        ulonglong2 w3h = *(const ulonglong2*)(wb + 3*4*wstr + g*8 + 4);
        #pragma unroll
        for (int kk = 0; kk < 4; kk++){
            const float* sp = st + (g*4 + kk)*64 + c0;
            ulonglong2 sa = *(const ulonglong2*)(sp);        // cols c0..c0+3
            ulonglong2 sb = *(const ulonglong2*)(sp + 32);   // cols c0+32..+35
            ull w0 = (kk==0)?w0l.x:(kk==1)?w0l.y:(kk==2)?w0h.x:w0h.y;
            ull w1 = (kk==0)?w1l.x:(kk==1)?w1l.y:(kk==2)?w1h.x:w1h.y;
            ull w2 = (kk==0)?w2l.x:(kk==1)?w2l.y:(kk==2)?w2h.x:w2h.y;
            ull w3 = (kk==0)?w3l.x:(kk==1)?w3l.y:(kk==2)?w3h.x:w3h.y;
            ffma2(acc[ 0], w0, sa.x); ffma2(acc[ 1], w0, sa.y);
            ffma2(acc[ 2], w0, sb.x); ffma2(acc[ 3], w0, sb.y);
            ffma2(acc[ 4], w1, sa.x); ffma2(acc[ 5], w1, sa.y);
            ffma2(acc[ 6], w1, sb.x); ffma2(acc[ 7], w1, sb.y);
            ffma2(acc[ 8], w2, sa.x); ffma2(acc[ 9], w2, sa.y);
            ffma2(acc[10], w2, sb.x); ffma2(acc[11], w2, sb.y);
            ffma2(acc[12], w3, sa.x); ffma2(acc[13], w3, sa.y);
            ffma2(acc[14], w3, sb.x); ffma2(acc[15], w3, sb.y);
        }
    }
}

extern "C" __global__ void __launch_bounds__(NTHR, 1)
lstm_bn_kernel(const float* __restrict__ x,
               const float* __restrict__ Wih,
               const float* __restrict__ Whh,
               const float* __restrict__ bias,
               const float* __restrict__ gIH, const float* __restrict__ bIH,
               const float* __restrict__ gHH, const float* __restrict__ bHH,
               const float* __restrict__ gC,  const float* __restrict__ bC,
               float* __restrict__ out, int T)
{
    extern __shared__ float sm[];
    float* whd    = sm + OFF_WHD;
    float* wid    = sm + OFF_WID;
    float* stage  = sm + OFF_ST;
    float* sg     = sm + OFF_SG;
    float* ghh_s  = sm + OFF_CST;
    float* bhh_s  = ghh_s + 16;
    float* gih_s  = bhh_s + 16;
    float* bih_s  = gih_s + 16;
    float* bias_s = bih_s + 16;
    float* gc_s   = bias_s + 16;
    float* bc_s   = gc_s + 4;

    const int tid  = threadIdx.x;
    const int blk  = blockIdx.x;
    const int w    = tid >> 5;          // warp 0..7 = k-slice within each chunk
    const int lane = tid & 31;
    const int rowg = lane >> 3;         // 0..3 -> rows {rowg, rowg+4, rowg+8, rowg+12}
    const int colg = lane & 7;          // 0..7 -> cols {colg*4..+3} ∪ {colg*4+32..+35}
    const int c0   = colg * 4;

    // ---- preload weights, DUPLICATED
    for (int idx = tid; idx < 16*HSZ; idx += NTHR){
        int l = idx >> 9, k = idx & 511;
        int grow = (l >> 2) * HSZ + blk*4 + (l & 3);
        float v = Whh[(size_t)grow * HSZ + k];
        whd[l*WHD_STR + 2*k]     = v;
        whd[l*WHD_STR + 2*k + 1] = v;
    }
    for (int idx = tid; idx < 16*ISZ; idx += NTHR){
        int l = idx >> 8, k = idx & 255;
        int grow = (l >> 2) * HSZ + blk*4 + (l & 3);
        float v = Wih[(size_t)grow * ISZ + k];
        wid[l*WID_STR + 2*k]     = v;
        wid[l*WID_STR + 2*k + 1] = v;
    }
    if (tid < 16){
        int grow = (tid >> 2) * HSZ + blk*4 + (tid & 3);
        ghh_s[tid] = gHH[grow]; bhh_s[tid] = bHH[grow];
        gih_s[tid] = gIH[grow]; bih_s[tid] = bIH[grow];
        bias_s[tid] = bias[grow];
    }
    if (tid < 4){ gc_s[tid] = gC[blk*4 + tid]; bc_s[tid] = bC[blk*4 + tid]; }

    g_h[0][blk * NTHR + tid] = 0.f;
    __syncthreads();

    unsigned gen0 = 0, my_gen = 0;
    if (tid == 0) gen0 = *((volatile unsigned*)&g_release);

    auto gridsync = [&](){
        __syncthreads();
        if (tid == 0){
            my_gen++;
            __threadfence();
            unsigned a = atomicAdd(&g_arrive, 1u);
            if (a == (unsigned)(NBLK - 1)){
                atomicExch(&g_arrive, 0u);
                __threadfence();
                atomicAdd(&g_release, 1u);
            } else {
                while ( (*((volatile unsigned*)&g_release)) - gen0 < my_gen ) { }
            }
        }
        __syncthreads();
    };

    gridsync();

    const uint32_t stBase = (uint32_t)__cvta_generic_to_shared(stage);
    const float inv64 = 1.0f / 64.0f;
    float creg0 = 0.f, creg1 = 0.f;
    const int lane32 = tid & 31;

    // weight base for this thread's rowg; k offset added per chunk
    const float* whb = whd + rowg*WHD_STR + w*16;   // w*8 k * 2 dup
    const float* wib = wid + rowg*WID_STR + w*16;
    const int stOff = w * 8 * 64;                   // k-slice within slot

    for (int t = 0; t < T; t++){
        const float* hrd = g_h[t & 1];
        float*       hwr = g_h[(t + 1) & 1];
        const float* xt  = x + (size_t)t * (ISZ*BSZ);

        ull accA[16], accB[16];
        #pragma unroll
        for (int i = 0; i < 16; i++){ accA[i] = 0; accB[i] = 0; }

        // prefetch chunks 0,1 into slots 0,1
        {
            #pragma unroll
            for (int j = 0; j < 4; j++){
                cp16(stBase +              (uint32_t)(tid + j*256)*16u, hrd +        (tid + j*256)*4);
                cp16(stBase + SLOT_BYTES + (uint32_t)(tid + j*256)*16u, hrd + 4096 + (tid + j*256)*4);
            }
            asm volatile("cp.async.commit_group;");
        }

        // 6 rounds; round r: ALL warps process chunks 2r and 2r+1 (8-k slice each)
        for (int r = 0; r < 6; r++){
            if (r < 5){
                int cA = 2*r + 2, cB = 2*r + 3;
                const float* srcA = (cA < 8) ? (hrd + cA*4096) : (xt + (cA-8)*4096);
                const float* srcB = (cB < 8) ? (hrd + cB*4096) : (xt + (cB-8)*4096);
                uint32_t dA = stBase + (uint32_t)(cA % 6) * SLOT_BYTES;
                uint32_t dB = stBase + (uint32_t)(cB % 6) * SLOT_BYTES;
                #pragma unroll
                for (int j = 0; j < 4; j++){
                    cp16(dA + (uint32_t)(tid + j*256)*16u, srcA + (tid + j*256)*4);
                    cp16(dB + (uint32_t)(tid + j*256)*16u, srcB + (tid + j*256)*4);
                }
                asm volatile("cp.async.commit_group;");
                asm volatile("cp.async.wait_group 1;");
            } else {
                asm volatile("cp.async.wait_group 0;");
            }
            __syncthreads();

            int c = 2*r;
            const float* st0 = stage + (c % 6) * 4096 + stOff;
            const float* st1 = stage + ((c+1) % 6) * 4096 + stOff;
            if (c < 8){   // rounds 0-3: both chunks hh
                gemm_slice(st0, whb + (c  )*128, WHD_STR, c0, accA);
                gemm_slice(st1, whb + (c+1)*128, WHD_STR, c0, accA);
            } else {      // rounds 4-5: both chunks ih
                gemm_slice(st0, wib + (c-8)*128, WID_STR, c0, accB);
                gemm_slice(st1, wib + (c-7)*128, WID_STR, c0, accB);
            }
        }

        __syncthreads();   // all slot reads done; reuse ring for partials

        // ---- write per-warp k-slice partials: pA = stage[0..8704), pB = stage[8704..17408)
        float* pA = stage;
        float* pB = stage + 8*16*PSTR;
        {
            float* ap = pA + w*(16*PSTR);
            float* bp = pB + w*(16*PSTR);
            #pragma unroll
            for (int j = 0; j < 4; j++){
                int rr = rowg + j*4;
                *(ulonglong2*)(ap + rr*PSTR + c0)      = make_ulonglong2(accA[j*4+0], accA[j*4+1]);
                *(ulonglong2*)(ap + rr*PSTR + c0 + 32) = make_ulonglong2(accA[j*4+2], accA[j*4+3]);
                *(ulonglong2*)(bp + rr*PSTR + c0)      = make_ulonglong2(accB[j*4+0], accB[j*4+1]);
                *(ulonglong2*)(bp + rr*PSTR + c0 + 32) = make_ulonglong2(accB[j*4+2], accB[j*4+3]);
            }
        }
        __syncthreads();

        // ---- reduce 8 k-slices + per-gate-row batchnorm
        // thread owns row rr = tid>>4 (0..15), cols c4 = (tid&15)*4
        {
            const int rr = tid >> 4, c4 = (tid & 15) * 4;
            ulonglong2 sa = *(const ulonglong2*)(pA + rr*PSTR + c4);
            ulonglong2 sb = *(const ulonglong2*)(pB + rr*PSTR + c4);
            ull ax = sa.x, ay = sa.y, bx = sb.x, by = sb.y;
            #pragma unroll
            for (int ww = 1; ww < 8; ww++){
                ulonglong2 qa = *(const ulonglong2*)(pA + ww*(16*PSTR) + rr*PSTR + c4);
                ulonglong2 qb = *(const ulonglong2*)(pB + ww*(16*PSTR) + rr*PSTR + c4);
                addf2(ax, qa.x); addf2(ay, qa.y);
                addf2(bx, qb.x); addf2(by, qb.y);
            }
            float vA[4], vB[4];
            unpack2(ax, vA[0], vA[1]); unpack2(ay, vA[2], vA[3]);
            unpack2(bx, vB[0], vB[1]); unpack2(by, vB[2], vB[3]);

            float sA = vA[0]+vA[1]+vA[2]+vA[3];
            float qA = vA[0]*vA[0]+vA[1]*vA[1]+vA[2]*vA[2]+vA[3]*vA[3];
            float sB = vB[0]+vB[1]+vB[2]+vB[3];
            float qB = vB[0]*vB[0]+vB[1]*vB[1]+vB[2]*vB[2]+vB[3]*vB[3];
            #pragma unroll
            for (int off = 1; off < 16; off <<= 1){
                sA += __shfl_xor_sync(0xffffffffu, sA, off);
                qA += __shfl_xor_sync(0xffffffffu, qA, off);
                sB += __shfl_xor_sync(0xffffffffu, sB, off);
                qB += __shfl_xor_sync(0xffffffffu, qB, off);
            }
            float muA = sA*inv64, muB = sB*inv64;
            float rsA = rsqrtf(qA*inv64 - muA*muA + EPSBN);
            float rsB = rsqrtf(qB*inv64 - muB*muB + EPSBN);
            float ga = ghh_s[rr]*rsA, gb = gih_s[rr]*rsB;
            float cadd = bhh_s[rr] + bih_s[rr] + bias_s[rr] - muA*ga - muB*gb;
            #pragma unroll
            for (int j = 0; j < 4; j++)
                sg[rr*64 + c4 + j] = fmaf(vA[j], ga, fmaf(vB[j], gb, cadd));
        }
        __syncthreads();

        // ---- phase B: gates + cell + c-BN + h (warps 0-3)
        if (w < 4){
            float iv0 = sg[( 0 + w)*64 + lane32], iv1 = sg[( 0 + w)*64 + lane32 + 32];
            float fv0 = sg[( 4 + w)*64 + lane32], fv1 = sg[( 4 + w)*64 + lane32 + 32];
            float gv0 = sg[( 8 + w)*64 + lane32], gv1 = sg[( 8 + w)*64 + lane32 + 32];
            float ov0 = sg[(12 + w)*64 + lane32], ov1 = sg[(12 + w)*64 + lane32 + 32];

            creg0 = sigm(fv0)*creg0 + sigm(iv0)*tanhf(gv0);
            creg1 = sigm(fv1)*creg1 + sigm(iv1)*tanhf(gv1);

            float sc = creg0 + creg1;
            float qc = creg0*creg0 + creg1*creg1;
            #pragma unroll
            for (int off = 16; off >= 1; off >>= 1){
                sc += __shfl_xor_sync(0xffffffffu, sc, off);
                qc += __shfl_xor_sync(0xffffffffu, qc, off);
            }
            float mu = sc*inv64;
            float rs = rsqrtf(qc*inv64 - mu*mu + EPSBN);
            float gcv = gc_s[w]*rs;
            float bcv = bc_s[w] - mu*gcv;
            float h0v = sigm(ov0) * tanhf(fmaf(creg0, gcv, bcv));
            float h1v = sigm(ov1) * tanhf(fmaf(creg1, gcv, bcv));

            int rowg2 = blk*4 + w;
            hwr[rowg2*64 + lane32]      = h0v;
            hwr[rowg2*64 + lane32 + 32] = h1v;
            float* op = out + (size_t)t * (HSZ*BSZ) + rowg2*64;
            op[lane32]      = h0v;
            op[lane32 + 32] = h1v;
        }

        gridsync();
    }
}

extern "C" void kernel_launch(void* const* d_in, const int* in_sizes, int n_in,
                              void* d_out, int out_size)
{
    const float* x    = (const float*)d_in[0];
    const float* Wih  = (const float*)d_in[1];
    const float* Whh  = (const float*)d_in[2];
    const float* bias = (const float*)d_in[3];
    const float* gIH  = (const float*)d_in[4];
    const float* bIH  = (const float*)d_in[5];
    const float* gHH  = (const float*)d_in[6];
    const float* bHH  = (const float*)d_in[7];
    const float* gC   = (const float*)d_in[8];
    const float* bC   = (const float*)d_in[9];
    float* out = (float*)d_out;

    int T = in_sizes[0] / (ISZ * BSZ);   // 2048

    cudaFuncSetAttribute(lstm_bn_kernel,
                         cudaFuncAttributeMaxDynamicSharedMemorySize, SMEM_BYTES);
    lstm_bn_kernel<<<NBLK, NTHR, SMEM_BYTES>>>(x, Wih, Whh, bias,
                                               gIH, bIH, gHH, bHH, gC, bC,
                                               out, T);
}